// round 13
// baseline (speedup 1.0000x reference)
#include <cuda_runtime.h>
#include <cstdint>

#define BATCH 32
#define HW    16384
#define NCLS  80
#define NPB   (HW * NCLS)    // 1310720
#define N4    (NPB / 4)      // 327680 float4 per batch
#define KTOP  100
#define BINS  2048
#define CAP   4096
#define SBUF  1024

#define GRID  148
#define TPB   1024

#define SAMPLE_STRIDE 64             // float4 stride -> 1/64 of elements
#define NSAMP4 (N4 / SAMPLE_STRIDE)  // 5120 float4 = 20480 samples/batch
#define GATHER_RANK 64               // gather enough samples for rank 48

// device scratch (zero-init, no allocation)
__device__ int          g_cnt[BATCH];
__device__ int          g_redo[BATCH];
__device__ float        g_thresh[BATCH];   // active threshold (t16, or retry)
__device__ float        g_thi[BATCH];      // rank-4 sample (tighter)
__device__ float        g_tlo[BATCH];      // rank-48 sample (looser)
__device__ int          g_flag;
__device__ uint2        g_cand[BATCH][CAP];
__device__ unsigned int g_bar_cnt;         // self-resetting -> replay-safe
__device__ unsigned int g_bar_gen;

__device__ __forceinline__ unsigned int f2key(float f) {
    unsigned int u = __float_as_uint(f);
    return (u & 0x80000000u) ? ~u : (u | 0x80000000u);
}
__device__ __forceinline__ unsigned int u2key(unsigned int u) {
    return (u & 0x80000000u) ? ~u : (u | 0x80000000u);
}
__device__ __forceinline__ float key2f(unsigned int k) {
    unsigned int u = (k & 0x80000000u) ? (k ^ 0x80000000u) : ~k;
    return __uint_as_float(u);
}

// Sense-reversing grid barrier. Counter self-resets each use, generation is
// monotonic across uses and replays -> safe under CUDA-graph replay.
__device__ __forceinline__ void grid_barrier() {
    __syncthreads();
    if (threadIdx.x == 0) {
        __threadfence();
        unsigned int gen = *((volatile unsigned int*)&g_bar_gen);
        unsigned int old = atomicAdd(&g_bar_cnt, 1);
        if (old == GRID - 1) {
            *((volatile unsigned int*)&g_bar_cnt) = 0;
            __threadfence();
            atomicAdd(&g_bar_gen, 1);
        } else {
            while (*((volatile unsigned int*)&g_bar_gen) == gen) {}
        }
        __threadfence();
    }
    __syncthreads();
}

__global__ __launch_bounds__(TPB, 1)
void fused_decode(const float* __restrict__ cls,
                  const float* __restrict__ loc,
                  float* __restrict__ out) {
    __shared__ union {
        struct {
            unsigned int sb[BINS];
            unsigned int csum[256];
            float        sbuf[SBUF];
        } p1;                       // 13 KB
        uint2 cand[CAP];            // 32 KB
    } sm;
    __shared__ int   s_n, s_cb;
    __shared__ float s_t[3];

    const int bid = blockIdx.x;
    const int t   = threadIdx.x;

    // ---------------- Phase 1: per-batch sampled thresholds ----------------
    if (bid < BATCH) {
        const int b = bid;
        for (int i = t; i < BINS; i += TPB) sm.p1.sb[i] = 0;
        if (t == 0) {
            s_n = 0;
            s_t[0] = s_t[1] = s_t[2] = __int_as_float(0xff800000); // -inf
            g_cnt[b]  = 0;
            g_redo[b] = 0;
            if (b == 0) g_flag = 0;
        }
        __syncthreads();

        const float4* p = (const float4*)(cls + (size_t)b * NPB);
        for (int k = t; k < NSAMP4; k += TPB) {
            float4 v = p[(size_t)k * SAMPLE_STRIDE];
            atomicAdd(&sm.p1.sb[f2key(v.x) >> 21], 1u);
            atomicAdd(&sm.p1.sb[f2key(v.y) >> 21], 1u);
            atomicAdd(&sm.p1.sb[f2key(v.z) >> 21], 1u);
            atomicAdd(&sm.p1.sb[f2key(v.w) >> 21], 1u);
        }
        __syncthreads();

        if (t < 256) {
            unsigned int s = 0;
            #pragma unroll
            for (int i = 0; i < 8; i++) s += sm.p1.sb[t * 8 + i];
            sm.p1.csum[t] = s;
        }
        __syncthreads();
        if (t == 0) {
            unsigned int acc = 0;
            int cb = 0;
            for (int c = 255; c >= 0; c--) {
                if (acc + sm.p1.csum[c] >= GATHER_RANK) {
                    for (int i = 7; i >= 0; i--) {
                        unsigned int bv = sm.p1.sb[c * 8 + i];
                        if (acc + bv >= GATHER_RANK) { cb = c * 8 + i; break; }
                        acc += bv;
                    }
                    break;
                }
                acc += sm.p1.csum[c];
            }
            s_cb = cb;
        }
        __syncthreads();
        const unsigned int cb = (unsigned int)s_cb;

        // gather sample values in bins >= cb (>= GATHER_RANK of them)
        for (int k = t; k < NSAMP4; k += TPB) {
            float4 v = p[(size_t)k * SAMPLE_STRIDE];
            #pragma unroll
            for (int j = 0; j < 4; j++) {
                float f = (j == 0) ? v.x : (j == 1) ? v.y : (j == 2) ? v.z : v.w;
                if ((f2key(f) >> 21) >= cb) {
                    int pos = atomicAdd(&s_n, 1);
                    if (pos < SBUF) sm.p1.sbuf[pos] = f;
                }
            }
        }
        __syncthreads();
        const int m = min(s_n, SBUF);

        // exact rank select at ranks 4, 16, 48 (stable tie-break by slot)
        for (int i = t; i < m; i += TPB) {
            float vi = sm.p1.sbuf[i];
            int r = 0;
            for (int j = 0; j < m; j++) {
                float vj = sm.p1.sbuf[j];
                r += (vj > vi) || (vj == vi && j < i);
            }
            if (r == 3)  s_t[0] = vi;
            if (r == 15) s_t[1] = vi;
            if (r == 47) s_t[2] = vi;
        }
        __syncthreads();
        if (t == 0) {
            g_thi[b]    = s_t[0];
            g_thresh[b] = s_t[1];
            g_tlo[b]    = s_t[2];
        }
    }
    grid_barrier();

    // ---------------- Phase 2: collect (all blocks, all batches) -----------
    {
        for (int b = 0; b < BATCH; b++) {
            const float Tf = g_thresh[b];
            const float4* p = (const float4*)(cls + (size_t)b * NPB);
            for (int i = bid * TPB + t; i < N4; i += GRID * TPB) {
                float4 v = __ldcs(p + i);
                #pragma unroll
                for (int j = 0; j < 4; j++) {
                    float val = (j == 0) ? v.x : (j == 1) ? v.y
                              : (j == 2) ? v.z : v.w;
                    if (val >= Tf) {
                        int pos = atomicAdd(&g_cnt[b], 1);
                        if (pos < CAP)
                            g_cand[b][pos] = make_uint2(__float_as_uint(val),
                                                        (unsigned int)(4 * i + j));
                    }
                }
            }
        }
    }
    grid_barrier();

    // ---------------- Phase 3: check + retarget bad batches -----------------
    if (bid == 0 && t < BATCH) {
        int c = g_cnt[t];
        if (c > CAP) {
            g_thresh[t] = g_thi[t];   // tighten
            g_cnt[t] = 0; g_redo[t] = 1; g_flag = 1;
        } else if (c < KTOP) {
            g_thresh[t] = g_tlo[t];   // loosen
            g_cnt[t] = 0; g_redo[t] = 1; g_flag = 1;
        }
    }
    grid_barrier();

    // ---------------- Phase 4: guarded re-collect (normally skipped) --------
    if (g_flag) {
        for (int b = 0; b < BATCH; b++) {
            if (!g_redo[b]) continue;
            const float Tf = g_thresh[b];
            const float4* p = (const float4*)(cls + (size_t)b * NPB);
            for (int i = bid * TPB + t; i < N4; i += GRID * TPB) {
                float4 v = __ldcs(p + i);
                #pragma unroll
                for (int j = 0; j < 4; j++) {
                    float val = (j == 0) ? v.x : (j == 1) ? v.y
                              : (j == 2) ? v.z : v.w;
                    if (val >= Tf) {
                        int pos = atomicAdd(&g_cnt[b], 1);
                        if (pos < CAP)
                            g_cand[b][pos] = make_uint2(__float_as_uint(val),
                                                        (unsigned int)(4 * i + j));
                    }
                }
            }
        }
    }
    grid_barrier();

    // ---------------- Phase 5: exact rank select + gather -------------------
    if (bid < BATCH) {
        const int b = bid;
        const int n = min(g_cnt[b], CAP);
        for (int i = t; i < n; i += TPB) sm.cand[i] = g_cand[b][i];
        __syncthreads();

        for (int i = t; i < n; i += TPB) {
            const unsigned int ki = u2key(sm.cand[i].x);
            const unsigned int xi = sm.cand[i].y;
            int rank = 0;
            for (int j = 0; j < n; j++) {
                unsigned int kj = u2key(sm.cand[j].x);
                unsigned int xj = sm.cand[j].y;
                rank += (kj > ki) || (kj == ki && xj < xi);
            }
            if (rank < KTOP) {
                unsigned int cls_id = xi % NCLS;
                unsigned int sp = xi / NCLS;
                float4 box = ((const float4*)(loc + (size_t)b * HW * 4))[sp];
                float* o = out + ((size_t)b * KTOP + rank) * 6;
                o[0] = box.x; o[1] = box.y; o[2] = box.z; o[3] = box.w;
                o[4] = key2f(ki);
                o[5] = (float)cls_id;
            }
        }
    }
}

// ---------------------------------------------------------------------------
extern "C" void kernel_launch(void* const* d_in, const int* in_sizes, int n_in,
                              void* d_out, int out_size) {
    const float* cls = (const float*)d_in[0];
    const float* loc = (const float*)d_in[1];
    if (n_in >= 2 && in_sizes[0] < in_sizes[1]) {
        cls = (const float*)d_in[1];
        loc = (const float*)d_in[0];
    }
    float* out = (float*)d_out;

    fused_decode<<<GRID, TPB>>>(cls, loc, out);
}

// round 15
// speedup vs baseline: 1.5326x; 1.5326x over previous
#include <cuda_runtime.h>
#include <cstdint>

#define BATCH 32
#define HW    16384
#define NCLS  80
#define NPB   (HW * NCLS)    // 1310720
#define N4    (NPB / 4)      // 327680 float4 per batch
#define KTOP  100
#define BINS  2048
#define CAP   4096
#define SBUF  1024

#define SAMPLE_STRIDE 64             // float4 stride -> 1/64 of elements
#define NSAMP4 (N4 / SAMPLE_STRIDE)  // 5120 float4 = 20480 samples/batch
#define GATHER_RANK 64               // gather covers rank 48 comfortably

// device scratch (no allocation allowed)
__device__ int          g_cnt[BATCH];
__device__ int          g_redo[BATCH];
__device__ unsigned int g_cutkey[BATCH];   // active threshold (key domain)
__device__ unsigned int g_khi[BATCH];      // rank-4 sample key (tighter)
__device__ unsigned int g_klo[BATCH];      // rank-48 sample key (looser)
__device__ int          g_flag;
__device__ uint2        g_cand[BATCH][CAP]; // (key, linear index)

__device__ __forceinline__ unsigned int f2key(float f) {
    unsigned int u = __float_as_uint(f);
    return (u & 0x80000000u) ? ~u : (u | 0x80000000u);
}
__device__ __forceinline__ float key2f(unsigned int k) {
    unsigned int u = (k & 0x80000000u) ? (k ^ 0x80000000u) : ~k;
    return __uint_as_float(u);
}

// ---------------------------------------------------------------------------
// Kernel 1: per-batch sampled thresholds at ranks 4/16/48 (exact sample
// values). One block of 1024 threads per batch. Also initializes state.
__global__ void sample_cut_kernel(const float* __restrict__ cls) {
    __shared__ unsigned int sb[BINS];
    __shared__ unsigned int csum[256];
    __shared__ float sbuf[SBUF];
    __shared__ int s_n, s_cb;
    __shared__ unsigned int s_k[3];
    const int b = blockIdx.x;
    const int t = threadIdx.x;

    for (int i = t; i < BINS; i += blockDim.x) sb[i] = 0;
    if (t == 0) {
        s_n = 0;
        s_k[0] = s_k[1] = s_k[2] = 0;
        g_cnt[b] = 0;
        g_redo[b] = 0;
        if (b == 0) g_flag = 0;
    }
    __syncthreads();

    const float4* p = (const float4*)(cls + (size_t)b * NPB);
    // coarse histogram of 20480 strided samples
    for (int k = t; k < NSAMP4; k += blockDim.x) {
        float4 v = p[(size_t)k * SAMPLE_STRIDE];
        atomicAdd(&sb[f2key(v.x) >> 21], 1u);
        atomicAdd(&sb[f2key(v.y) >> 21], 1u);
        atomicAdd(&sb[f2key(v.z) >> 21], 1u);
        atomicAdd(&sb[f2key(v.w) >> 21], 1u);
    }
    __syncthreads();

    if (t < 256) {
        unsigned int s = 0;
        #pragma unroll
        for (int i = 0; i < 8; i++) s += sb[t * 8 + i];
        csum[t] = s;
    }
    __syncthreads();
    if (t == 0) {
        unsigned int acc = 0;
        int cb = 0;
        for (int c = 255; c >= 0; c--) {
            if (acc + csum[c] >= GATHER_RANK) {
                for (int i = 7; i >= 0; i--) {
                    unsigned int bv = sb[c * 8 + i];
                    if (acc + bv >= GATHER_RANK) { cb = c * 8 + i; break; }
                    acc += bv;
                }
                break;
            }
            acc += csum[c];
        }
        s_cb = cb;
    }
    __syncthreads();
    const unsigned int cb = (unsigned int)s_cb;

    // gather sample values in bins >= cb  (>= GATHER_RANK of them)
    for (int k = t; k < NSAMP4; k += blockDim.x) {
        float4 v = p[(size_t)k * SAMPLE_STRIDE];
        #pragma unroll
        for (int j = 0; j < 4; j++) {
            float f = (j == 0) ? v.x : (j == 1) ? v.y : (j == 2) ? v.z : v.w;
            if ((f2key(f) >> 21) >= cb) {
                int pos = atomicAdd(&s_n, 1);
                if (pos < SBUF) sbuf[pos] = f;
            }
        }
    }
    __syncthreads();
    const int m = min(s_n, SBUF);

    // exact rank select at ranks 4, 16, 48 (stable tie-break by slot)
    for (int i = t; i < m; i += blockDim.x) {
        float vi = sbuf[i];
        int r = 0;
        for (int j = 0; j < m; j++) {
            float vj = sbuf[j];
            r += (vj > vi) || (vj == vi && j < i);
        }
        if (r == 3)  s_k[0] = f2key(vi);
        if (r == 15) s_k[1] = f2key(vi);
        if (r == 47) s_k[2] = f2key(vi);
    }
    __syncthreads();
    if (t == 0) {
        g_khi[b]    = s_k[0];
        g_cutkey[b] = s_k[1];
        g_klo[b]    = s_k[2];
    }
}

// ---------------------------------------------------------------------------
// Kernel 2/4: collect — EXACT replica of the proven-fast R2 loop (plain
// loads, key compare, rare predicated global atomic). No __ldcs.
__global__ void collect_kernel(const float* __restrict__ cls, int mode) {
    const int b = blockIdx.y;
    if (mode == 1 && (g_flag == 0 || g_redo[b] == 0)) return;
    const unsigned int cut = g_cutkey[b];
    const float4* p = (const float4*)(cls + (size_t)b * NPB);
    const int stride = gridDim.x * blockDim.x;

    for (int i = blockIdx.x * blockDim.x + threadIdx.x; i < N4; i += stride) {
        float4 v = p[i];
        unsigned int ks[4] = { f2key(v.x), f2key(v.y), f2key(v.z), f2key(v.w) };
        #pragma unroll
        for (int j = 0; j < 4; j++) {
            if (ks[j] >= cut) {
                int pos = atomicAdd(&g_cnt[b], 1);
                if (pos < CAP)
                    g_cand[b][pos] = make_uint2(ks[j], (unsigned int)(4 * i + j));
            }
        }
    }
}

// ---------------------------------------------------------------------------
// Kernel 3: verify counts; retarget bad batches to precomputed alternates.
__global__ void check_kernel() {
    const int t = threadIdx.x;   // 32 threads
    if (t < BATCH) {
        int c = g_cnt[t];
        if (c > CAP) {           // too many -> tighten to rank-4 key
            g_cutkey[t] = g_khi[t];
            g_cnt[t] = 0; g_redo[t] = 1;
        } else if (c < KTOP) {   // too few -> loosen to rank-48 key
            g_cutkey[t] = g_klo[t];
            g_cnt[t] = 0; g_redo[t] = 1;
        }
    }
    __syncwarp();
    unsigned int m = __ballot_sync(0xffffffffu, t < BATCH && g_redo[t]);
    if (t == 0 && m) g_flag = 1;
}

// ---------------------------------------------------------------------------
// Kernel 5: exact rank (key desc, index asc = jax top_k), gather boxes.
__global__ void select_kernel(const float* __restrict__ loc,
                              float* __restrict__ out) {
    __shared__ uint2 cand[CAP];
    const int b = blockIdx.x;
    const int n = min(g_cnt[b], CAP);
    for (int i = threadIdx.x; i < n; i += blockDim.x) cand[i] = g_cand[b][i];
    __syncthreads();

    for (int i = threadIdx.x; i < n; i += blockDim.x) {
        const unsigned int ki = cand[i].x;
        const unsigned int xi = cand[i].y;
        int rank = 0;
        for (int j = 0; j < n; j++) {
            unsigned int kj = cand[j].x;
            unsigned int xj = cand[j].y;
            rank += (kj > ki) || (kj == ki && xj < xi);
        }
        if (rank < KTOP) {
            unsigned int cls_id = xi % NCLS;
            unsigned int sp = xi / NCLS;
            float4 box = ((const float4*)(loc + (size_t)b * HW * 4))[sp];
            float* o = out + ((size_t)b * KTOP + rank) * 6;
            o[0] = box.x; o[1] = box.y; o[2] = box.z; o[3] = box.w;
            o[4] = key2f(ki);
            o[5] = (float)cls_id;
        }
    }
}

// ---------------------------------------------------------------------------
extern "C" void kernel_launch(void* const* d_in, const int* in_sizes, int n_in,
                              void* d_out, int out_size) {
    const float* cls = (const float*)d_in[0];
    const float* loc = (const float*)d_in[1];
    if (n_in >= 2 && in_sizes[0] < in_sizes[1]) {
        cls = (const float*)d_in[1];
        loc = (const float*)d_in[0];
    }
    float* out = (float*)d_out;

    sample_cut_kernel<<<BATCH, 1024>>>(cls);
    collect_kernel<<<dim3(128, BATCH), 256>>>(cls, 0);
    check_kernel<<<1, 32>>>();
    collect_kernel<<<dim3(128, BATCH), 256>>>(cls, 1);  // no-op normally
    select_kernel<<<BATCH, 1024>>>(loc, out);
}